// round 8
// baseline (speedup 1.0000x reference)
#include <cuda_runtime.h>
#include <math.h>
#include <stdint.h>

// Shapes (fixed by the problem)
#define T_STEPS 32
#define NB      64
#define CDIM    512
#define F1DIM   2048
#define F2DIM   1024
#define F3DIM   512

typedef unsigned long long ull;

// ---------------- scratch (device globals; no allocation allowed) -------------
__device__ float g_F1[T_STEPS * NB * CDIM];
__device__ float g_H1[T_STEPS * NB * F1DIM];
__device__ float g_F2[T_STEPS * NB * F1DIM];
__device__ float g_H2[T_STEPS * NB * F2DIM];
__device__ float g_F3[T_STEPS * NB * F2DIM];
__device__ float g_H3[T_STEPS * NB * F3DIM];

__device__ __forceinline__ float sigmoid_acc(float w) {
    return 1.0f / (1.0f + expf(-w));
}

// ---------------------------------------------------------------------------
// Stage 1 (verbatim from passing R1/R7)
// ---------------------------------------------------------------------------
__global__ void stage1_kernel(const float* __restrict__ x,
                              const float* __restrict__ w_jeff,
                              const float* __restrict__ w_cc,
                              const float* __restrict__ w_sf0,
                              const float* __restrict__ w_sf1)
{
    int gw   = (blockIdx.x * blockDim.x + threadIdx.x) >> 5;
    int lane = threadIdx.x & 31;
    if (gw >= NB * CDIM) return;
    int n = gw / CDIM;
    int c = gw - n * CDIM;

    float wj0 = w_jeff[lane * 2 + 0];
    float wj1 = w_jeff[lane * 2 + 1];
    float wcc = w_cc[lane];
    float d0  = 1.0f - sigmoid_acc(w_sf0[0]);
    float d1  = 1.0f - sigmoid_acc(w_sf1[0]);
    const float invlif = 1.0f / 1.5f;

    float yf0 = 0.f, yf1 = 0.f;
    float v = 0.f, g = 0.f, vI = 0.f, fo = 0.f;

    const float* xb = x + (size_t)n * 2 * CDIM + c;
#pragma unroll
    for (int t = 0; t < T_STEPS; t++) {
        float x0 = xb[(size_t)t * NB * 2 * CDIM];
        float x1 = xb[(size_t)t * NB * 2 * CDIM + CDIM];
        yf0 = 0.5f * yf0 + x0;
        yf1 = 0.5f * yf1 + x1;
        float u = wj0 * yf0 + wj1 * yf1;
        v = v + (u - v) * invlif;
        float s = (v >= 1.0f) ? 1.0f : 0.0f;
        v = (v >= 1.0f) ? 0.0f : v;
        g = d0 * g + s;
        float r = g * wcc;
#pragma unroll
        for (int off = 16; off; off >>= 1)
            r += __shfl_xor_sync(0xffffffffu, r, off);
        vI += r;
        float s1 = (vI >= 1.0f) ? 1.0f : 0.0f;
        vI = (vI >= 1.0f) ? 0.0f : vI;
        fo = d1 * fo + s1;
        if (lane == 0)
            g_F1[((size_t)t * NB + n) * CDIM + c] = fo;
    }
}

// ---------------------------------------------------------------------------
// FP32 GEMM (NT), packed f32x2 FMA, bit-identical sequential-k chains.
// C[m][o] = sum_k A[o][k] * B[m][k]
// Tile: 128 (o) x 64 (m), BK=16, 128 threads, 8x8 microtile per thread.
// Grid doubled vs R7 => 2-4 CTAs/SM co-resident (occupancy fix).
// ---------------------------------------------------------------------------
#define PADA 132    // floats per k-row of As (128 o + 4)
#define PADB 68     // floats per k-row of Bs (64 m + 4)

#define FMA2(acc, a, b) \
    asm("fma.rn.f32x2 %0, %1, %2, %0;" : "+l"(acc) : "l"(a), "l"(b))
#define PACK_DUP(d, s) \
    asm("mov.b64 %0, {%1, %1};" : "=l"(d) : "f"(s))
#define UNPACK2(lo, hi, v) \
    asm("mov.b64 {%0, %1}, %2;" : "=f"(lo), "=f"(hi) : "l"(v))

__global__ void __launch_bounds__(128, 4)
gemm_x2_kernel(const float* __restrict__ A, const float* __restrict__ B,
               float* __restrict__ C, int Mo, int K)
{
    __shared__ float As[2][16 * PADA];   // [k][o]
    __shared__ float Bs[2][16 * PADB];   // [k][m]

    int tid = threadIdx.x;
    int tx  = tid & 7;          // m-microtile index (0..7)
    int ty  = tid >> 3;         // o-microtile index (0..15)
    int bo  = blockIdx.x * 128; // o tile
    int bn  = blockIdx.y * 64;  // m (batch) tile
    int NC  = K / 16;

    // Loaders: every thread owns A-row (bo+tid); threads<64 also own B-row.
    const float* gA = A + (size_t)(bo + tid) * K;
    const bool  bld = (tid < 64);
    const float* gB = B + (size_t)(bn + (tid & 63)) * K;

    ull acc[4][8];
#pragma unroll
    for (int i = 0; i < 4; i++)
#pragma unroll
        for (int j = 0; j < 8; j++) acc[i][j] = 0ULL;

    float4 a0, a1, a2, a3, b0, b1, b2, b3;
    a0 = *(const float4*)(gA + 0);
    a1 = *(const float4*)(gA + 4);
    a2 = *(const float4*)(gA + 8);
    a3 = *(const float4*)(gA + 12);
    if (bld) {
        b0 = *(const float4*)(gB + 0);
        b1 = *(const float4*)(gB + 4);
        b2 = *(const float4*)(gB + 8);
        b3 = *(const float4*)(gB + 12);
    }

    for (int c = 0; c < NC; c++) {
        int buf = c & 1;
        {
            float* colA = &As[buf][tid];
            colA[0 * PADA]  = a0.x; colA[1 * PADA]  = a0.y;
            colA[2 * PADA]  = a0.z; colA[3 * PADA]  = a0.w;
            colA[4 * PADA]  = a1.x; colA[5 * PADA]  = a1.y;
            colA[6 * PADA]  = a1.z; colA[7 * PADA]  = a1.w;
            colA[8 * PADA]  = a2.x; colA[9 * PADA]  = a2.y;
            colA[10 * PADA] = a2.z; colA[11 * PADA] = a2.w;
            colA[12 * PADA] = a3.x; colA[13 * PADA] = a3.y;
            colA[14 * PADA] = a3.z; colA[15 * PADA] = a3.w;
            if (bld) {
                float* colB = &Bs[buf][tid & 63];
                colB[0 * PADB]  = b0.x; colB[1 * PADB]  = b0.y;
                colB[2 * PADB]  = b0.z; colB[3 * PADB]  = b0.w;
                colB[4 * PADB]  = b1.x; colB[5 * PADB]  = b1.y;
                colB[6 * PADB]  = b1.z; colB[7 * PADB]  = b1.w;
                colB[8 * PADB]  = b2.x; colB[9 * PADB]  = b2.y;
                colB[10 * PADB] = b2.z; colB[11 * PADB] = b2.w;
                colB[12 * PADB] = b3.x; colB[13 * PADB] = b3.y;
                colB[14 * PADB] = b3.z; colB[15 * PADB] = b3.w;
            }
        }
        __syncthreads();

        if (c + 1 < NC) {
            const float* pA = gA + (c + 1) * 16;
            a0 = *(const float4*)(pA + 0);
            a1 = *(const float4*)(pA + 4);
            a2 = *(const float4*)(pA + 8);
            a3 = *(const float4*)(pA + 12);
            if (bld) {
                const float* pB = gB + (c + 1) * 16;
                b0 = *(const float4*)(pB + 0);
                b1 = *(const float4*)(pB + 4);
                b2 = *(const float4*)(pB + 8);
                b3 = *(const float4*)(pB + 12);
            }
        }

#pragma unroll
        for (int k = 0; k < 16; k++) {
            const float* as = &As[buf][k * PADA + ty * 8];
            const float* bs = &Bs[buf][k * PADB + tx * 8];
            ulonglong2 t0 = *(const ulonglong2*)as;
            ulonglong2 t1 = *(const ulonglong2*)(as + 4);
            float4 v0 = *(const float4*)bs;
            float4 v1 = *(const float4*)(bs + 4);
            ull aP[4] = {t0.x, t0.y, t1.x, t1.y};
            ull bb[8];
            PACK_DUP(bb[0], v0.x); PACK_DUP(bb[1], v0.y);
            PACK_DUP(bb[2], v0.z); PACK_DUP(bb[3], v0.w);
            PACK_DUP(bb[4], v1.x); PACK_DUP(bb[5], v1.y);
            PACK_DUP(bb[6], v1.z); PACK_DUP(bb[7], v1.w);
#pragma unroll
            for (int j = 0; j < 8; j++)
#pragma unroll
                for (int i = 0; i < 4; i++)
                    FMA2(acc[i][j], aP[i], bb[j]);
        }
        __syncthreads();
    }

    // Epilogue: row m = bn + tx*8 + j, cols o = bo + ty*8 .. +7
#pragma unroll
    for (int j = 0; j < 8; j++) {
        float r0, r1, r2, r3, r4, r5, r6, r7;
        UNPACK2(r0, r1, acc[0][j]);
        UNPACK2(r2, r3, acc[1][j]);
        UNPACK2(r4, r5, acc[2][j]);
        UNPACK2(r6, r7, acc[3][j]);
        float* cp = C + (size_t)(bn + tx * 8 + j) * Mo + bo + ty * 8;
        *reinterpret_cast<float4*>(cp + 0) = make_float4(r0, r1, r2, r3);
        *reinterpret_cast<float4*>(cp + 4) = make_float4(r4, r5, r6, r7);
    }
}

// ---------------------------------------------------------------------------
// IFNode + SynapseFilter fused (verbatim from R1/R7).
// ---------------------------------------------------------------------------
__global__ void ifsyn_kernel(const float* __restrict__ H, float* __restrict__ F,
                             const float* __restrict__ w_sf, int Odim)
{
    int idx = blockIdx.x * blockDim.x + threadIdx.x;
    if (idx >= NB * Odim) return;
    int o = idx % Odim;
    int n = idx / Odim;
    float d = 1.0f - sigmoid_acc(w_sf[0]);
    float v = 0.f, f = 0.f;
#pragma unroll
    for (int t = 0; t < T_STEPS; t++) {
        size_t id = ((size_t)t * NB + n) * Odim + o;
        v += H[id];
        float s = (v >= 1.0f) ? 1.0f : 0.0f;
        v = (v >= 1.0f) ? 0.0f : v;
        f = d * f + s;
        F[id] = f;
    }
}

// ---------------------------------------------------------------------------
// Final kernel (verbatim from R1/R7).
// ---------------------------------------------------------------------------
__global__ void final_kernel(const float* __restrict__ Wout,
                             const float* __restrict__ bout,
                             float* __restrict__ out)
{
    int n = blockIdx.x;
    int f = threadIdx.x;
    __shared__ float red[16];
    float v   = 0.f;
    float wf  = Wout[f];
    float acc = 0.f;
    float b   = bout[0];
    int lane = f & 31, wid = f >> 5;
    for (int t = 0; t < T_STEPS; t++) {
        v += g_H3[((size_t)t * NB + n) * F3DIM + f];
        float s = (v >= 1.0f) ? 1.0f : 0.0f;
        v = (v >= 1.0f) ? 0.0f : v;
        float p = wf * s;
#pragma unroll
        for (int off = 16; off; off >>= 1)
            p += __shfl_xor_sync(0xffffffffu, p, off);
        if (lane == 0) red[wid] = p;
        __syncthreads();
        if (f < 16) {
            float q = red[f];
#pragma unroll
            for (int off = 8; off; off >>= 1)
                q += __shfl_xor_sync(0x0000ffffu, q, off);
            if (f == 0) {
                acc += q + b;
                out[t * NB + n] = acc;
            }
        }
        __syncthreads();
    }
}

// ---------------------------------------------------------------------------
extern "C" void kernel_launch(void* const* d_in, const int* in_sizes, int n_in,
                              void* d_out, int out_size)
{
    (void)in_sizes; (void)n_in; (void)out_size;
    const float* x     = (const float*)d_in[0];
    const float* wjeff = (const float*)d_in[1];
    const float* wcc   = (const float*)d_in[2];
    const float* wsf0  = (const float*)d_in[3];
    const float* W1    = (const float*)d_in[4];
    const float* wsf1  = (const float*)d_in[5];
    const float* W2    = (const float*)d_in[6];
    const float* wsf2  = (const float*)d_in[7];
    const float* W3    = (const float*)d_in[8];
    const float* wsf3  = (const float*)d_in[9];
    const float* Wout  = (const float*)d_in[10];
    const float* bout  = (const float*)d_in[11];
    float* out = (float*)d_out;

    float *F1, *H1, *F2, *H2, *F3, *H3;
    cudaGetSymbolAddress((void**)&F1, g_F1);
    cudaGetSymbolAddress((void**)&H1, g_H1);
    cudaGetSymbolAddress((void**)&F2, g_F2);
    cudaGetSymbolAddress((void**)&H2, g_H2);
    cudaGetSymbolAddress((void**)&F3, g_F3);
    cudaGetSymbolAddress((void**)&H3, g_H3);

    // Stage 1: one warp per (n,c)
    stage1_kernel<<<(NB * CDIM * 32) / 256, 256>>>(x, wjeff, wcc, wsf0, wsf1);

    // Block 1: W1 @ F1 -> H1 ; IF + filter(w_sf2) -> F2   grid (16,32)=512
    gemm_x2_kernel<<<dim3(F1DIM / 128, (T_STEPS * NB) / 64), 128>>>(W1, F1, H1, F1DIM, CDIM);
    ifsyn_kernel<<<(NB * F1DIM + 255) / 256, 256>>>(H1, F2, wsf2, F1DIM);

    // Block 2: grid (8,32)=256
    gemm_x2_kernel<<<dim3(F2DIM / 128, (T_STEPS * NB) / 64), 128>>>(W2, F2, H2, F2DIM, F1DIM);
    ifsyn_kernel<<<(NB * F2DIM + 255) / 256, 256>>>(H2, F3, wsf3, F2DIM);

    // Block 3: grid (4,32)=128
    gemm_x2_kernel<<<dim3(F3DIM / 128, (T_STEPS * NB) / 64), 128>>>(W3, F3, H3, F3DIM, F2DIM);

    // Final linear + NonSpikingIF cumsum
    final_kernel<<<NB, F3DIM>>>(Wout, bout, out);
}